// round 2
// baseline (speedup 1.0000x reference)
#include <cuda_runtime.h>
#include <cuda_bf16.h>
#include <cstdint>

// Problem constants (from reference)
#define S_    8
#define U_    8
#define K_    12
#define NEG_  17
#define ZD    64
#define CD    256
#define T_    1140
#define LEN   1128
#define SU    64            // S_*U_
#define TOTPOS 72192        // SU*LEN

// ---------------- scratch (static device globals; no runtime alloc) ----------------
__device__ float  g_Wc[(size_t)K_ * TOTPOS * ZD];   // [k][su*LEN + l][z]  ~222 MB
__device__ double g_loss[K_];
__device__ double g_acc[K_];

// ---------------- zero accumulators ----------------
__global__ void zero_accum() {
    int i = threadIdx.x;
    if (i < K_) { g_loss[i] = 0.0; g_acc[i] = 0.0; }
}

// ---------------- GEMM: Wc[k][su][l][:] = c[su][l][:] @ W[k][:][:]^T + b[k][:] ----------------
// Tiles: BM=128 (l), BN=64 (z, = full k-slice), BK=16. 256 threads, 8x4 per thread.
#define BM 128
#define BN 64
#define BK 16

__global__ __launch_bounds__(256) void gemm_wc(const float* __restrict__ C,
                                               const float* __restrict__ W,
                                               const float* __restrict__ Bias) {
    __shared__ float As[BK][BM + 4];
    __shared__ float Bs[BK][BN + 4];

    const int k  = blockIdx.x;   // 0..11  (fastest => consecutive blocks reuse c tile in L2)
    const int lt = blockIdx.y;   // 0..8
    const int su = blockIdx.z;   // 0..63
    const int l0 = lt * BM;
    const int tid = threadIdx.x;
    const int tx = tid & 15;     // n / 4
    const int ty = tid >> 4;     // m / 8

    const float* Ag = C + ((size_t)su * T_ + l0) * CD;
    const float* Bg = W + (size_t)k * ZD * CD;

    float acc[8][4];
#pragma unroll
    for (int i = 0; i < 8; i++)
#pragma unroll
        for (int j = 0; j < 4; j++) acc[i][j] = 0.0f;

    for (int kt = 0; kt < CD; kt += BK) {
        // load A tile: 128 rows x 16 cols = 512 float4; 2 per thread
#pragma unroll
        for (int r = 0; r < 2; ++r) {
            int f   = r * 256 + tid;
            int row = f >> 2;
            int c4  = f & 3;
            float4 v = make_float4(0.f, 0.f, 0.f, 0.f);
            if (l0 + row < LEN)
                v = *(const float4*)(Ag + (size_t)row * CD + kt + c4 * 4);
            As[c4 * 4 + 0][row] = v.x;
            As[c4 * 4 + 1][row] = v.y;
            As[c4 * 4 + 2][row] = v.z;
            As[c4 * 4 + 3][row] = v.w;
        }
        // load B tile: 64 rows x 16 cols = 256 float4; 1 per thread
        {
            int n  = tid >> 2;
            int c4 = tid & 3;
            float4 v = *(const float4*)(Bg + (size_t)n * CD + kt + c4 * 4);
            Bs[c4 * 4 + 0][n] = v.x;
            Bs[c4 * 4 + 1][n] = v.y;
            Bs[c4 * 4 + 2][n] = v.z;
            Bs[c4 * 4 + 3][n] = v.w;
        }
        __syncthreads();

#pragma unroll
        for (int kk = 0; kk < BK; ++kk) {
            float4 a0 = *(const float4*)&As[kk][ty * 8 + 0];
            float4 a1 = *(const float4*)&As[kk][ty * 8 + 4];
            float4 bv = *(const float4*)&Bs[kk][tx * 4];
            float a[8] = {a0.x, a0.y, a0.z, a0.w, a1.x, a1.y, a1.z, a1.w};
            float b[4] = {bv.x, bv.y, bv.z, bv.w};
#pragma unroll
            for (int i = 0; i < 8; i++)
#pragma unroll
                for (int j = 0; j < 4; j++) acc[i][j] += a[i] * b[j];
        }
        __syncthreads();
    }

    const float4 bias = *(const float4*)(Bias + k * ZD + tx * 4);
    float* outp = g_Wc + ((size_t)k * TOTPOS + (size_t)su * LEN) * ZD;
#pragma unroll
    for (int i = 0; i < 8; i++) {
        int l = l0 + ty * 8 + i;
        if (l < LEN) {
            float4 o;
            o.x = acc[i][0] + bias.x;
            o.y = acc[i][1] + bias.y;
            o.z = acc[i][2] + bias.z;
            o.w = acc[i][3] + bias.w;
            *(float4*)(outp + (size_t)l * ZD + tx * 4) = o;
        }
    }
}

// ---------------- CPC loss: per (k, su, l) logsumexp over {pos, 17 negs} ----------------
// Reference k_ref = kernel k + 1; prediction rows are at t = l + k + 1.
// Warp layout: 4 groups of 8 lanes; each group owns one l. Lane lg of a group
// loads bytes [16*lg,16*lg+16) and [128+16*lg,...) of each 256B row (coalesced:
// 2 L1tex wavefronts per row). Dot reduced by 3 shfl.bfly inside the group.
#define BLOCKS_PER_K 2256   // 18048 warps/k / 8 warps/block ; 18048 = 64 su * 282 ltiles

__global__ __launch_bounds__(256) void cpc_loss(const float* __restrict__ z,
                                                const int* __restrict__ batch_index,
                                                const int* __restrict__ seq_index) {
    const int wid  = threadIdx.x >> 5;
    const int lane = threadIdx.x & 31;
    const int grp  = lane >> 3;
    const int lg   = lane & 7;

    const int k   = blockIdx.x / BLOCKS_PER_K;
    const int rem = blockIdx.x % BLOCKS_PER_K;
    const int wg  = rem * 8 + wid;          // 0..18047 within this k
    const int su  = wg / 282;
    const int l   = (wg % 282) * 4 + grp;   // 282*4 == 1128, always in range
    const int s   = su >> 3;
    const int u   = su & 7;
    const int kshift = k + 1;               // reference k in [1..12]

    // Wc row (64 floats): this lane's 8 floats
    const float* wc = g_Wc + ((size_t)k * TOTPOS + (size_t)su * LEN + l) * ZD;
    const float4 wa = *(const float4*)(wc + 4 * lg);
    const float4 wb = *(const float4*)(wc + 32 + 4 * lg);

    // positive sample: z[su, l + kshift, :]
    const float* zp = z + ((size_t)(su * T_ + l + kshift)) * ZD;
    float4 za = *(const float4*)(zp + 4 * lg);
    float4 zb = *(const float4*)(zp + 32 + 4 * lg);
    float v = wa.x * za.x + wa.y * za.y + wa.z * za.z + wa.w * za.w
            + wb.x * zb.x + wb.y * zb.y + wb.z * zb.z + wb.w * zb.w;
    v += __shfl_xor_sync(0xffffffffu, v, 1);
    v += __shfl_xor_sync(0xffffffffu, v, 2);
    v += __shfl_xor_sync(0xffffffffu, v, 4);
    const float pos = v * 0.125f;

    // prefetch all indices (independent loads -> high MLP)
    const int* bip = batch_index + (k * U_ + u) * NEG_;
    const int* sip = seq_index + ((size_t)((k * S_ + s) * U_ + u) * NEG_) * LEN + l;
    int bis[NEG_], sis[NEG_];
#pragma unroll
    for (int n = 0; n < NEG_; n++) {
        bis[n] = __ldg(bip + n);
        sis[n] = __ldg(sip + (size_t)n * LEN);
    }

    float m = pos, ssum = 1.0f, ok = 1.0f;
#pragma unroll
    for (int n = 0; n < NEG_; n++) {
        const float* zr = z + ((size_t)((s * 8 + bis[n]) * T_ + sis[n] + kshift)) * ZD;
        float4 na = *(const float4*)(zr + 4 * lg);
        float4 nb = *(const float4*)(zr + 32 + 4 * lg);
        float d = wa.x * na.x + wa.y * na.y + wa.z * na.z + wa.w * na.w
                + wb.x * nb.x + wb.y * nb.y + wb.z * nb.z + wb.w * nb.w;
        d += __shfl_xor_sync(0xffffffffu, d, 1);
        d += __shfl_xor_sync(0xffffffffu, d, 2);
        d += __shfl_xor_sync(0xffffffffu, d, 4);
        d *= 0.125f;
        if (d > pos) ok = 0.0f;                 // argmax==0 iff pos >= every neg
        if (d > m) { ssum = ssum * __expf(m - d) + 1.0f; m = d; }
        else       { ssum += __expf(d - m); }
    }

    float lt = m + __logf(ssum) - pos;          // log_z - f0

    // sum the 4 groups of this warp (values uniform within each group)
    lt += __shfl_xor_sync(0xffffffffu, lt, 8);
    lt += __shfl_xor_sync(0xffffffffu, lt, 16);
    ok += __shfl_xor_sync(0xffffffffu, ok, 8);
    ok += __shfl_xor_sync(0xffffffffu, ok, 16);

    __shared__ float sL[8], sA[8];
    if (lane == 0) { sL[wid] = lt; sA[wid] = ok; }
    __syncthreads();
    if (threadIdx.x == 0) {
        float L = 0.f, A = 0.f;
#pragma unroll
        for (int i = 0; i < 8; i++) { L += sL[i]; A += sA[i]; }
        atomicAdd(&g_loss[k], (double)L);
        atomicAdd(&g_acc[k], (double)A);
    }
}

// ---------------- finalize: out[0] = loss, out[1..12] = accs ----------------
__global__ void finalize(float* __restrict__ out, int out_size) {
    if (threadIdx.x == 0) {
        double tot = 0.0;
#pragma unroll
        for (int kk = 0; kk < K_; kk++) tot += g_loss[kk];
        if (out_size > 0) out[0] = (float)(tot / ((double)K_ * (double)TOTPOS));
#pragma unroll
        for (int kk = 0; kk < K_; kk++)
            if (1 + kk < out_size) out[1 + kk] = (float)(g_acc[kk] / (double)TOTPOS);
    }
}

// ---------------- launch ----------------
extern "C" void kernel_launch(void* const* d_in, const int* in_sizes, int n_in,
                              void* d_out, int out_size) {
    const float* z  = (const float*)d_in[0];
    const float* c  = (const float*)d_in[1];
    const float* W  = (const float*)d_in[2];
    const float* b  = (const float*)d_in[3];
    const int* bidx = (const int*)d_in[4];
    const int* sidx = (const int*)d_in[5];

    zero_accum<<<1, 32>>>();

    dim3 ggrid(K_, 9, SU);            // k fastest -> c-tile L2 reuse across k
    gemm_wc<<<ggrid, 256>>>(c, W, b);

    cpc_loss<<<K_ * BLOCKS_PER_K, 256>>>(z, bidx, sidx);

    finalize<<<1, 32>>>((float*)d_out, out_size);
}